// round 16
// baseline (speedup 1.0000x reference)
#include <cuda_runtime.h>
#include <cstdint>

// AI4DEM coupling_backward: 3x3 tent-spline gather, 4096x4096 periodic grid.
// Inputs: xp, yp, x_grid(unused), y_grid(unused), vx, vy, Fx, Fy, mask
// Output: 5 planes [alpha, alpha_u, alpha_v, Fx, Fy], each 4096*4096 f32.
//
//   per tap: w = max(0,1-|xp_src - x_dst|) * max(0,1-|yp_src - y_dst|)
//   out     = mask_dst * VP * sum(w * field_src)     (mask at DESTINATION)
//
// R16 = R11 (champion) + cross-block L2 prefetch: right after committing its
// own cp.async staging, each block prefetch.global.L2's the tile of block
// (blockIdx + 888) -- the block that will start as this one finishes
// (888 = 148 SMs x 6 resident blocks). That block's staging then hits L2
// (~280cyc) instead of DRAM (~600-1000cyc), shrinking the per-block
// stage-wait bubble (the measured ~10-14% gap to the DRAM-floor wall).
// L2-as-pipeline-buffer: zero register / smem / issue cost (~3 prefetch
// instrs per thread), unlike the failed intra-block pipelines (R8/R9).

#define NXD   4096
#define MASKW 4095

#define BLK_T    128          // threads per block
#define OUT_ROWS 8            // output rows per block
#define SRC_ROWS 10           // OUT_ROWS + 2 halo rows
#define ROWW     136          // 4 pad | 128 main | 4 pad  (floats)
#define ROWVECS  34           // ROWW / 4 float4s per field-row
#define VECS_PER_FIELD (SRC_ROWS * ROWVECS)   // 340
#define MK_VECS  (OUT_ROWS * 32)              // 256 float4s of mask
#define AHEAD    888          // 148 SMs x 6 blocks/SM
#define NBLK     (32 * 512)

__device__ __forceinline__ void cpa16(uint32_t saddr, const float* g) {
    asm volatile("cp.async.cg.shared.global [%0], [%1], 16;\n"
                 :: "r"(saddr), "l"(g));
}

__device__ __forceinline__ void pfL2(const char* g) {
    asm volatile("prefetch.global.L2 [%0];\n" :: "l"(g));
}

__device__ __forceinline__ float tent(float d) {
    return fmaxf(1.0f - fabsf(d), 0.0f);
}

__device__ __forceinline__ constexpr int kmin_of(int s) { return (s - 2 > 0) ? (s - 2) : 0; }
__device__ __forceinline__ constexpr int kmax_of(int s) { return (s < 3) ? s : 3; }

__global__ void __launch_bounds__(BLK_T, 6)
ai4dem_kernel(const float* __restrict__ xp, const float* __restrict__ yp,
              const float* __restrict__ vx, const float* __restrict__ vy,
              const float* __restrict__ Fx, const float* __restrict__ Fy,
              const float* __restrict__ mk, float* __restrict__ out)
{
    const float VP = 3.1415f / 6.0f;

    __shared__ float sm[6][SRC_ROWS][ROWW];   // 32,640 B
    __shared__ float smk[OUT_ROWS][128];      //  4,096 B

    const int t   = threadIdx.x;
    const int bx  = blockIdx.x & 31;          // 32 col-blocks
    const int by  = blockIdx.x >> 5;          // 512 row-blocks
    const int xb0 = bx << 7;                  // block's first col
    const int y0b = by << 3;                  // block's first out row

    const float* fptr[6] = {xp, yp, vx, vy, Fx, Fy};

    // ---- stage 6 fields x 10 rows x 136 cols + mask 8x128 via cp.async ----
    {
        #pragma unroll
        for (int f = 0; f < 6; ++f) {
            const float* base = fptr[f];
            #pragma unroll
            for (int j = t; j < VECS_PER_FIELD; j += BLK_T) {
                int rr = j / ROWVECS;                 // 0..9
                int v  = j - rr * ROWVECS;            // 0..33
                int gy = (y0b - 1 + rr) & MASKW;
                int gx = (xb0 - 4 + (v << 2)) & MASKW;   // 16B-aligned, wraps whole
                uint32_t sa = (uint32_t)__cvta_generic_to_shared(&sm[f][rr][v << 2]);
                cpa16(sa, base + ((size_t)gy << 12) + gx);
            }
        }
        // mask: 8 rows x 128 cols, aligned, no halo
        #pragma unroll
        for (int j = t; j < MK_VECS; j += BLK_T) {
            int rr = j >> 5;                          // 0..7
            int v  = j & 31;                          // 0..31
            uint32_t sa = (uint32_t)__cvta_generic_to_shared(&smk[rr][v << 2]);
            cpa16(sa, mk + ((size_t)(y0b + rr) << 12) + xb0 + (v << 2));
        }
        asm volatile("cp.async.commit_group;\n" ::: "memory");
    }

    // ---- L2-prefetch the tile of block (blockIdx + AHEAD) ----
    {
        int pb = blockIdx.x + AHEAD;
        if (pb < NBLK) {
            const int pbx0 = (pb & 31) << 7;          // its first col
            const int py0b = (pb >> 5) << 3;          // its first out row
            // fields: 6 x 10 rows x 6 lines (768B aligned window covers 544B)
            const uint32_t b0 = (uint32_t)(((pbx0 << 2) - 16) & 16383) & ~127u;
            for (int j = t; j < 360; j += BLK_T) {
                int f   = j / 60;
                int rem = j - f * 60;
                int rr  = rem / 6;
                int li  = rem - rr * 6;
                int gy  = (py0b - 1 + rr) & MASKW;
                uint32_t boff = (b0 + ((uint32_t)li << 7)) & 16383u;
                pfL2(reinterpret_cast<const char*>(fptr[f]) + ((size_t)gy << 14) + boff);
            }
            // mask: 8 rows x 4 lines (512B per row, aligned)
            if (t < 32) {
                int rr = t >> 2;
                int li = t & 3;
                pfL2(reinterpret_cast<const char*>(mk) +
                     ((size_t)(py0b + rr) << 14) + ((uint32_t)(pbx0 << 2) + ((uint32_t)li << 7)));
            }
        }
    }

    asm volatile("cp.async.wait_group 0;\n" ::: "memory");
    __syncthreads();

    // ---- compute: each thread a 2x4 output tile ----
    const int tx = t & 31;                    // col quad within block
    const int ty = t >> 5;                    // row pair within block (0..3)
    const int xl = tx << 2;                   // local col offset
    const int xb = xb0 + xl;                  // global base col
    const int y0 = y0b + (ty << 1);           // global first out row

    const float fy0 = (float)y0;
    const float fy1 = (float)(y0 + 1);
    const float xk0 = (float)xb;
    const float xdst[4] = {xk0, xk0 + 1.0f, xk0 + 2.0f, xk0 + 3.0f};

    float aA[2][4] = {{0.f,0.f,0.f,0.f},{0.f,0.f,0.f,0.f}};
    float aU[2][4] = {{0.f,0.f,0.f,0.f},{0.f,0.f,0.f,0.f}};
    float aV[2][4] = {{0.f,0.f,0.f,0.f},{0.f,0.f,0.f,0.f}};
    float aX[2][4] = {{0.f,0.f,0.f,0.f},{0.f,0.f,0.f,0.f}};
    float aY[2][4] = {{0.f,0.f,0.f,0.f},{0.f,0.f,0.f,0.f}};

    #pragma unroll
    for (int r = 0; r < 4; ++r) {             // src rows y0-1 .. y0+2
        const int sr = (ty << 1) + r;         // smem row 0..9

        // tent support: src row r reaches dst rows within distance 1
        const int dmin = (r == 3) ? 1 : 0;
        const int dmax = (r == 0) ? 0 : 1;

        // coords -> weights (xp/yp regs die immediately)
        float ny[2][6];
        float nx[12];
        {
            float4 qx = *reinterpret_cast<const float4*>(&sm[0][sr][4 + xl]);
            float xl0 = sm[0][sr][3 + xl], xr0 = sm[0][sr][8 + xl];
            float4 qy = *reinterpret_cast<const float4*>(&sm[1][sr][4 + xl]);
            float yl0 = sm[1][sr][3 + xl], yr0 = sm[1][sr][8 + xl];
            float xps[6] = {xl0, qx.x, qx.y, qx.z, qx.w, xr0};
            float yps[6] = {yl0, qy.x, qy.y, qy.z, qy.w, yr0};
            int idx = 0;
            #pragma unroll
            for (int s = 0; s < 6; ++s) {
                #pragma unroll
                for (int d = dmin; d <= dmax; ++d)
                    ny[d][s] = tent(yps[s] - (d ? fy1 : fy0));
                #pragma unroll
                for (int k = kmin_of(s); k <= kmax_of(s); ++k)
                    nx[idx++] = tent(xps[s] - xdst[k]);
            }
        }

        // vx / vy + alpha
        {
            float4 qu = *reinterpret_cast<const float4*>(&sm[2][sr][4 + xl]);
            float ul = sm[2][sr][3 + xl], ur = sm[2][sr][8 + xl];
            float4 qv = *reinterpret_cast<const float4*>(&sm[3][sr][4 + xl]);
            float vl = sm[3][sr][3 + xl], vr = sm[3][sr][8 + xl];
            float vxs[6] = {ul, qu.x, qu.y, qu.z, qu.w, ur};
            float vys[6] = {vl, qv.x, qv.y, qv.z, qv.w, vr};
            int idx = 0;
            #pragma unroll
            for (int s = 0; s < 6; ++s) {
                const int i0 = idx;
                #pragma unroll
                for (int d = dmin; d <= dmax; ++d) {
                    float n  = ny[d][s];
                    float tu = n * vxs[s];
                    float tv = n * vys[s];
                    int ii = i0;
                    #pragma unroll
                    for (int k = kmin_of(s); k <= kmax_of(s); ++k, ++ii) {
                        float w = nx[ii];
                        aA[d][k] = fmaf(w, n,  aA[d][k]);
                        aU[d][k] = fmaf(w, tu, aU[d][k]);
                        aV[d][k] = fmaf(w, tv, aV[d][k]);
                    }
                }
                idx += kmax_of(s) - kmin_of(s) + 1;
            }
        }

        // Fx / Fy
        {
            float4 qa = *reinterpret_cast<const float4*>(&sm[4][sr][4 + xl]);
            float al = sm[4][sr][3 + xl], ar = sm[4][sr][8 + xl];
            float4 qb = *reinterpret_cast<const float4*>(&sm[5][sr][4 + xl]);
            float bl = sm[5][sr][3 + xl], br = sm[5][sr][8 + xl];
            float fxs[6] = {al, qa.x, qa.y, qa.z, qa.w, ar};
            float fys[6] = {bl, qb.x, qb.y, qb.z, qb.w, br};
            int idx = 0;
            #pragma unroll
            for (int s = 0; s < 6; ++s) {
                const int i0 = idx;
                #pragma unroll
                for (int d = dmin; d <= dmax; ++d) {
                    float n   = ny[d][s];
                    float txv = n * fxs[s];
                    float tyv = n * fys[s];
                    int ii = i0;
                    #pragma unroll
                    for (int k = kmin_of(s); k <= kmax_of(s); ++k, ++ii) {
                        float w = nx[ii];
                        aX[d][k] = fmaf(w, txv, aX[d][k]);
                        aY[d][k] = fmaf(w, tyv, aY[d][k]);
                    }
                }
                idx += kmax_of(s) - kmin_of(s) + 1;
            }
        }
    }

    // ---- mask (from smem, staged) * VP, then store 5 planes ----
    const size_t P = (size_t)NXD * NXD;
    #pragma unroll
    for (int d = 0; d < 2; ++d) {
        size_t o = ((size_t)(y0 + d) << 12) + xb;
        float4 mq = *reinterpret_cast<const float4*>(&smk[(ty << 1) + d][xl]);
        float md[4] = {mq.x * VP, mq.y * VP, mq.z * VP, mq.w * VP};

        #pragma unroll
        for (int k = 0; k < 4; ++k) {
            aA[d][k] *= md[k]; aU[d][k] *= md[k]; aV[d][k] *= md[k];
            aX[d][k] *= md[k]; aY[d][k] *= md[k];
        }

        *reinterpret_cast<float4*>(out + o)         = make_float4(aA[d][0], aA[d][1], aA[d][2], aA[d][3]);
        *reinterpret_cast<float4*>(out + P + o)     = make_float4(aU[d][0], aU[d][1], aU[d][2], aU[d][3]);
        *reinterpret_cast<float4*>(out + 2 * P + o) = make_float4(aV[d][0], aV[d][1], aV[d][2], aV[d][3]);
        *reinterpret_cast<float4*>(out + 3 * P + o) = make_float4(aX[d][0], aX[d][1], aX[d][2], aX[d][3]);
        *reinterpret_cast<float4*>(out + 4 * P + o) = make_float4(aY[d][0], aY[d][1], aY[d][2], aY[d][3]);
    }
}

extern "C" void kernel_launch(void* const* d_in, const int* in_sizes, int n_in,
                              void* d_out, int out_size)
{
    const float* xp = (const float*)d_in[0];
    const float* yp = (const float*)d_in[1];
    // d_in[2] = x_grid, d_in[3] = y_grid: analytic (x, y), not needed.
    const float* vx = (const float*)d_in[4];
    const float* vy = (const float*)d_in[5];
    const float* Fx = (const float*)d_in[6];
    const float* Fy = (const float*)d_in[7];
    const float* mk = (const float*)d_in[8];
    float* out = (float*)d_out;

    // 32 col-blocks x 512 row-blocks; each block: 128 cols x 8 rows of output
    ai4dem_kernel<<<NBLK, BLK_T>>>(xp, yp, vx, vy, Fx, Fy, mk, out);
}

// round 17
// speedup vs baseline: 1.0935x; 1.0935x over previous
#include <cuda_runtime.h>
#include <cstdint>

// AI4DEM coupling_backward: 3x3 tent-spline gather, 4096x4096 periodic grid.
// Inputs: xp, yp, x_grid(unused), y_grid(unused), vx, vy, Fx, Fy, mask
// Output: 5 planes [alpha, alpha_u, alpha_v, Fx, Fy], each 4096*4096 f32.
//
//   per tap: w = max(0,1-|xp_src - x_dst|) * max(0,1-|yp_src - y_dst|)
//   out     = mask_dst * VP * sum(w * field_src)     (mask at DESTINATION)
//
// R17 = R11 (champion) + LDS.64 halo reads. The per-field-row smem reads
// were 1x LDS.128 (4 crossbar cyc) + 2 scalar halo LDS whose 16B lane
// stride spans 512B = 4 cyc EACH (8 of 12 cycles for 2 useful floats).
// Loading each halo as an 8B-aligned float2 (take .y / .x) halves the span:
// per field-row 12 -> 8 crossbar cycles, kernel LDS cycles -33%, no new
// registers or dependencies.

#define NXD   4096
#define MASKW 4095

#define BLK_T    128          // threads per block
#define OUT_ROWS 8            // output rows per block
#define SRC_ROWS 10           // OUT_ROWS + 2 halo rows
#define ROWW     136          // 4 pad | 128 main | 4 pad  (floats)
#define ROWVECS  34           // ROWW / 4 float4s per field-row
#define VECS_PER_FIELD (SRC_ROWS * ROWVECS)   // 340
#define MK_VECS  (OUT_ROWS * 32)              // 256 float4s of mask

__device__ __forceinline__ void cpa16(uint32_t saddr, const float* g) {
    asm volatile("cp.async.cg.shared.global [%0], [%1], 16;\n"
                 :: "r"(saddr), "l"(g));
}

__device__ __forceinline__ float tent(float d) {
    return fmaxf(1.0f - fabsf(d), 0.0f);
}

__device__ __forceinline__ constexpr int kmin_of(int s) { return (s - 2 > 0) ? (s - 2) : 0; }
__device__ __forceinline__ constexpr int kmax_of(int s) { return (s < 3) ? s : 3; }

// read cols xl-1 .. xl+4 of one staged field-row:
//   main 4 via LDS.128 at [4+xl]; halos via 8B-aligned LDS.64 at [2+xl]/[8+xl]
__device__ __forceinline__ void row6(const float* rowp, int xl, float v[6]) {
    float4 q  = *reinterpret_cast<const float4*>(rowp + 4 + xl);
    float2 hl = *reinterpret_cast<const float2*>(rowp + 2 + xl);
    float2 hr = *reinterpret_cast<const float2*>(rowp + 8 + xl);
    v[0] = hl.y;
    v[1] = q.x; v[2] = q.y; v[3] = q.z; v[4] = q.w;
    v[5] = hr.x;
}

__global__ void __launch_bounds__(BLK_T, 6)
ai4dem_kernel(const float* __restrict__ xp, const float* __restrict__ yp,
              const float* __restrict__ vx, const float* __restrict__ vy,
              const float* __restrict__ Fx, const float* __restrict__ Fy,
              const float* __restrict__ mk, float* __restrict__ out)
{
    const float VP = 3.1415f / 6.0f;

    __shared__ float sm[6][SRC_ROWS][ROWW];   // 32,640 B
    __shared__ float smk[OUT_ROWS][128];      //  4,096 B

    const int t   = threadIdx.x;
    const int bx  = blockIdx.x & 31;          // 32 col-blocks
    const int by  = blockIdx.x >> 5;          // 512 row-blocks
    const int xb0 = bx << 7;                  // block's first col
    const int y0b = by << 3;                  // block's first out row

    // ---- stage 6 fields x 10 rows x 136 cols + mask 8x128 via cp.async ----
    {
        const float* fptr[6] = {xp, yp, vx, vy, Fx, Fy};
        #pragma unroll
        for (int f = 0; f < 6; ++f) {
            const float* base = fptr[f];
            #pragma unroll
            for (int j = t; j < VECS_PER_FIELD; j += BLK_T) {
                int rr = j / ROWVECS;                 // 0..9
                int v  = j - rr * ROWVECS;            // 0..33
                int gy = (y0b - 1 + rr) & MASKW;
                int gx = (xb0 - 4 + (v << 2)) & MASKW;   // 16B-aligned, wraps whole
                uint32_t sa = (uint32_t)__cvta_generic_to_shared(&sm[f][rr][v << 2]);
                cpa16(sa, base + ((size_t)gy << 12) + gx);
            }
        }
        // mask: 8 rows x 128 cols, aligned, no halo
        #pragma unroll
        for (int j = t; j < MK_VECS; j += BLK_T) {
            int rr = j >> 5;                          // 0..7
            int v  = j & 31;                          // 0..31
            uint32_t sa = (uint32_t)__cvta_generic_to_shared(&smk[rr][v << 2]);
            cpa16(sa, mk + ((size_t)(y0b + rr) << 12) + xb0 + (v << 2));
        }
        asm volatile("cp.async.commit_group;\n" ::: "memory");
        asm volatile("cp.async.wait_group 0;\n" ::: "memory");
        __syncthreads();
    }

    // ---- compute: each thread a 2x4 output tile ----
    const int tx = t & 31;                    // col quad within block
    const int ty = t >> 5;                    // row pair within block (0..3)
    const int xl = tx << 2;                   // local col offset
    const int xb = xb0 + xl;                  // global base col
    const int y0 = y0b + (ty << 1);           // global first out row

    const float fy0 = (float)y0;
    const float fy1 = (float)(y0 + 1);
    const float xk0 = (float)xb;
    const float xdst[4] = {xk0, xk0 + 1.0f, xk0 + 2.0f, xk0 + 3.0f};

    float aA[2][4] = {{0.f,0.f,0.f,0.f},{0.f,0.f,0.f,0.f}};
    float aU[2][4] = {{0.f,0.f,0.f,0.f},{0.f,0.f,0.f,0.f}};
    float aV[2][4] = {{0.f,0.f,0.f,0.f},{0.f,0.f,0.f,0.f}};
    float aX[2][4] = {{0.f,0.f,0.f,0.f},{0.f,0.f,0.f,0.f}};
    float aY[2][4] = {{0.f,0.f,0.f,0.f},{0.f,0.f,0.f,0.f}};

    #pragma unroll
    for (int r = 0; r < 4; ++r) {             // src rows y0-1 .. y0+2
        const int sr = (ty << 1) + r;         // smem row 0..9

        // tent support: src row r reaches dst rows within distance 1
        const int dmin = (r == 3) ? 1 : 0;
        const int dmax = (r == 0) ? 0 : 1;

        // coords -> weights (xp/yp regs die immediately)
        float ny[2][6];
        float nx[12];
        {
            float xps[6], yps[6];
            row6(&sm[0][sr][0], xl, xps);
            row6(&sm[1][sr][0], xl, yps);
            int idx = 0;
            #pragma unroll
            for (int s = 0; s < 6; ++s) {
                #pragma unroll
                for (int d = dmin; d <= dmax; ++d)
                    ny[d][s] = tent(yps[s] - (d ? fy1 : fy0));
                #pragma unroll
                for (int k = kmin_of(s); k <= kmax_of(s); ++k)
                    nx[idx++] = tent(xps[s] - xdst[k]);
            }
        }

        // vx / vy + alpha
        {
            float vxs[6], vys[6];
            row6(&sm[2][sr][0], xl, vxs);
            row6(&sm[3][sr][0], xl, vys);
            int idx = 0;
            #pragma unroll
            for (int s = 0; s < 6; ++s) {
                const int i0 = idx;
                #pragma unroll
                for (int d = dmin; d <= dmax; ++d) {
                    float n  = ny[d][s];
                    float tu = n * vxs[s];
                    float tv = n * vys[s];
                    int ii = i0;
                    #pragma unroll
                    for (int k = kmin_of(s); k <= kmax_of(s); ++k, ++ii) {
                        float w = nx[ii];
                        aA[d][k] = fmaf(w, n,  aA[d][k]);
                        aU[d][k] = fmaf(w, tu, aU[d][k]);
                        aV[d][k] = fmaf(w, tv, aV[d][k]);
                    }
                }
                idx += kmax_of(s) - kmin_of(s) + 1;
            }
        }

        // Fx / Fy
        {
            float fxs[6], fys[6];
            row6(&sm[4][sr][0], xl, fxs);
            row6(&sm[5][sr][0], xl, fys);
            int idx = 0;
            #pragma unroll
            for (int s = 0; s < 6; ++s) {
                const int i0 = idx;
                #pragma unroll
                for (int d = dmin; d <= dmax; ++d) {
                    float n   = ny[d][s];
                    float txv = n * fxs[s];
                    float tyv = n * fys[s];
                    int ii = i0;
                    #pragma unroll
                    for (int k = kmin_of(s); k <= kmax_of(s); ++k, ++ii) {
                        float w = nx[ii];
                        aX[d][k] = fmaf(w, txv, aX[d][k]);
                        aY[d][k] = fmaf(w, tyv, aY[d][k]);
                    }
                }
                idx += kmax_of(s) - kmin_of(s) + 1;
            }
        }
    }

    // ---- mask (from smem, staged) * VP, then store 5 planes ----
    const size_t P = (size_t)NXD * NXD;
    #pragma unroll
    for (int d = 0; d < 2; ++d) {
        size_t o = ((size_t)(y0 + d) << 12) + xb;
        float4 mq = *reinterpret_cast<const float4*>(&smk[(ty << 1) + d][xl]);
        float md[4] = {mq.x * VP, mq.y * VP, mq.z * VP, mq.w * VP};

        #pragma unroll
        for (int k = 0; k < 4; ++k) {
            aA[d][k] *= md[k]; aU[d][k] *= md[k]; aV[d][k] *= md[k];
            aX[d][k] *= md[k]; aY[d][k] *= md[k];
        }

        *reinterpret_cast<float4*>(out + o)         = make_float4(aA[d][0], aA[d][1], aA[d][2], aA[d][3]);
        *reinterpret_cast<float4*>(out + P + o)     = make_float4(aU[d][0], aU[d][1], aU[d][2], aU[d][3]);
        *reinterpret_cast<float4*>(out + 2 * P + o) = make_float4(aV[d][0], aV[d][1], aV[d][2], aV[d][3]);
        *reinterpret_cast<float4*>(out + 3 * P + o) = make_float4(aX[d][0], aX[d][1], aX[d][2], aX[d][3]);
        *reinterpret_cast<float4*>(out + 4 * P + o) = make_float4(aY[d][0], aY[d][1], aY[d][2], aY[d][3]);
    }
}

extern "C" void kernel_launch(void* const* d_in, const int* in_sizes, int n_in,
                              void* d_out, int out_size)
{
    const float* xp = (const float*)d_in[0];
    const float* yp = (const float*)d_in[1];
    // d_in[2] = x_grid, d_in[3] = y_grid: analytic (x, y), not needed.
    const float* vx = (const float*)d_in[4];
    const float* vy = (const float*)d_in[5];
    const float* Fx = (const float*)d_in[6];
    const float* Fy = (const float*)d_in[7];
    const float* mk = (const float*)d_in[8];
    float* out = (float*)d_out;

    // 32 col-blocks x 512 row-blocks; each block: 128 cols x 8 rows of output
    ai4dem_kernel<<<32 * 512, BLK_T>>>(xp, yp, vx, vy, Fx, Fy, mk, out);
}